// round 12
// baseline (speedup 1.0000x reference)
#include <cuda_runtime.h>
#include <cuda_fp16.h>
#include <math.h>
#include <stdint.h>

#define BB 64
#define LL 128
#define DD 200
#define MPP 20
#define ATTN 50
#define OC 83

typedef unsigned long long ull;

// ---------------- scratch ----------------
__device__ __align__(16) float g_e_rt[BB * LL * ATTN];
__device__ __align__(16) float g_e_lt[BB * LL * ATTN];

// -------- packed fp32x2 helpers --------
__device__ __forceinline__ ull ffma2u(ull a, ull b, ull c) {
    ull d;
    asm("fma.rn.f32x2 %0, %1, %2, %3;" : "=l"(d) : "l"(a), "l"(b), "l"(c));
    return d;
}
__device__ __forceinline__ ull addp2(ull a, ull b) {
    ull d;
    asm("add.rn.f32x2 %0, %1, %2;" : "=l"(d) : "l"(a), "l"(b));
    return d;
}
__device__ __forceinline__ ull bcast2(float x) {
    ull r;
    asm("mov.b64 %0, {%1, %1};" : "=l"(r) : "f"(x));
    return r;
}
__device__ __forceinline__ float2 unpack2(ull v) {
    float2 f;
    asm("mov.b64 {%0, %1}, %2;" : "=f"(f.x), "=f"(f.y) : "l"(v));
    return f;
}

// -------- warp MMA helpers --------
__device__ __forceinline__ uint32_t smem_to_u32(const void* p) {
    uint32_t a;
    asm("{ .reg .u64 t; cvta.to.shared.u64 t, %1; cvt.u32.u64 %0, t; }" : "=r"(a) : "l"(p));
    return a;
}
__device__ __forceinline__ void ldsm_x4(uint32_t* r, uint32_t addr) {
    asm volatile("ldmatrix.sync.aligned.m8n8.x4.shared.b16 {%0,%1,%2,%3}, [%4];"
                 : "=r"(r[0]), "=r"(r[1]), "=r"(r[2]), "=r"(r[3]) : "r"(addr));
}
__device__ __forceinline__ void mma16816(float* c, const uint32_t* a, const uint32_t* b) {
    asm volatile(
        "mma.sync.aligned.m16n8k16.row.col.f32.f16.f16.f32 "
        "{%0,%1,%2,%3}, {%4,%5,%6,%7}, {%8,%9}, {%0,%1,%2,%3};"
        : "+f"(c[0]), "+f"(c[1]), "+f"(c[2]), "+f"(c[3])
        : "r"(a[0]), "r"(a[1]), "r"(a[2]), "r"(a[3]), "r"(b[0]), "r"(b[1]));
}

// ================= projK: attention projections (standalone, runs first) ======
#define SMEM_PROJ ((DD * ATTN + ATTN * 128) * 4)
__global__ __launch_bounds__(256) void projK(
        const float* __restrict__ lt, const float* __restrict__ rt,
        const float* __restrict__ w1, const float* __restrict__ w2,
        const float* __restrict__ diag) {
    extern __shared__ float sm[];
    float* ws = sm;            // [200][50]
    float* pbuf = sm + DD * ATTN;  // [50][128]
    int b = blockIdx.x, side = blockIdx.y, tid = threadIdx.x;
    const float* wsrc = side == 0 ? w1 : w2;
    for (int i = tid; i < DD * ATTN; i += 256) ws[i] = wsrc[i];
    __syncthreads();
    int l = tid & 127, dh = tid >> 7;
    const float* base = side == 0 ? rt : lt;
    const float4* row = (const float4*)(base + (size_t)(b * LL + l) * DD + dh * 100);
    ull acc[ATTN / 2];
#pragma unroll
    for (int a = 0; a < ATTN / 2; a++) acc[a] = 0ULL;
    for (int d4 = 0; d4 < 25; d4++) {
        float4 x = __ldg(row + d4);
        int d = dh * 100 + d4 * 4;
#pragma unroll
        for (int c = 0; c < 4; c++) {
            float xc = (c == 0) ? x.x : (c == 1) ? x.y : (c == 2) ? x.z : x.w;
            ull x2 = bcast2(xc);
            const ull* wr = (const ull*)&ws[(d + c) * ATTN];
#pragma unroll
            for (int a = 0; a < ATTN / 2; a++) acc[a] = ffma2u(x2, wr[a], acc[a]);
        }
    }
    if (dh == 1) {
#pragma unroll
        for (int a = 0; a < ATTN / 2; a++) {
            float2 f = unpack2(acc[a]);
            pbuf[(2 * a) * 128 + l] = f.x;
            pbuf[(2 * a + 1) * 128 + l] = f.y;
        }
    }
    __syncthreads();
    if (dh == 0) {
        float* e = (side == 0 ? g_e_rt : g_e_lt) + (size_t)(b * LL + l) * ATTN;
#pragma unroll
        for (int a = 0; a < ATTN / 2; a++) {
            float2 f = unpack2(acc[a]);
            float v0 = tanhf(f.x + pbuf[(2 * a) * 128 + l]);
            float v1 = tanhf(f.y + pbuf[(2 * a + 1) * 128 + l]);
            if (side == 0) {
                v0 *= __ldg(diag + 2 * a);
                v1 *= __ldg(diag + 2 * a + 1);
            }
            e[2 * a] = v0;
            e[2 * a + 1] = v1;
        }
    }
}

// ======================================================================
// maxpool: CTA = (b, m-group of 5). Plain fp16 A x B (single pass).
// ======================================================================
#define STRD 216
#define TILE_B (LL * STRD * 2)
#define OFF_A 0
#define OFF_B (TILE_B)
#define SMEM_MP (2 * TILE_B)            // 110592
#define MGRP 5

__device__ __forceinline__ void maxpool_block(
        const float* __restrict__ lt, const float* __restrict__ rt,
        const float* __restrict__ w, float* __restrict__ out,
        int b, int mg0, char* smc, float (*red)[4]) {
    uint32_t sbase = smem_to_u32(smc);
    int tid = threadIdx.x, lane = tid & 31, wid = tid >> 5;

    for (int i = tid; i < 128 * 4; i += 512) {
        int r = i >> 2, c = i & 3;
        int off = (r * STRD + 200 + 2 * c) * 2;
        *(uint32_t*)(smc + OFF_A + off) = 0;
        *(uint32_t*)(smc + OFF_B + off) = 0;
    }
    const float* ltb = lt + (size_t)b * LL * DD;
    const float* rtb = rt + (size_t)b * LL * DD;
    for (int i = tid; i < LL * 100; i += 512) {
        int r = i / 100, k = (i - r * 100) * 2;
        float2 x = *(const float2*)(ltb + r * DD + k);
        __half2 h2 = __float22half2_rn(x);
        *(uint32_t*)(smc + OFF_A + (r * STRD + k) * 2) = *(uint32_t*)&h2;
    }

    int mbase = (wid >> 2) * 32, nbase = (wid & 3) * 32;
    int a_row = lane & 15;
    int a_col8 = (lane & 16) ? 8 : 0;
    int b_row = (lane & 7) + ((lane & 16) ? 8 : 0);
    int b_col8 = (lane & 8) ? 8 : 0;
    int wc = wid & 3;

#pragma unroll 1
    for (int mg = 0; mg < MGRP; mg++) {
        int m = mg0 + mg;
        const float* wm = w + (size_t)m * DD;
        for (int i = tid; i < LL * 100; i += 512) {
            int r = i / 100, k = (i - r * 100) * 2;
            float2 xb = *(const float2*)(rtb + r * DD + k);
            float2 ww = *(const float2*)(wm + k);
            __half2 h2 = __float22half2_rn(make_float2(xb.x * ww.x, xb.y * ww.y));
            *(uint32_t*)(smc + OFF_B + (r * STRD + k) * 2) = *(uint32_t*)&h2;
        }
        __syncthreads();

        float acc[2][4][4];
#pragma unroll
        for (int mt = 0; mt < 2; mt++)
#pragma unroll
            for (int nt = 0; nt < 4; nt++)
#pragma unroll
                for (int q = 0; q < 4; q++) acc[mt][nt][q] = 0.f;

#pragma unroll 1
        for (int kg = 0; kg < 13; kg++) {
            int kc = kg * 16;
            uint32_t ah[2][4];
#pragma unroll
            for (int mt = 0; mt < 2; mt++) {
                uint32_t row = mbase + 16 * mt + a_row;
                ldsm_x4(ah[mt], sbase + OFF_A + (row * STRD + kc + a_col8) * 2);
            }
#pragma unroll
            for (int np = 0; np < 2; np++) {
                uint32_t row = nbase + np * 16 + b_row;
                uint32_t bh[4];
                ldsm_x4(bh, sbase + OFF_B + (row * STRD + kc + b_col8) * 2);
#pragma unroll
                for (int mt = 0; mt < 2; mt++) {
                    mma16816(acc[mt][2 * np], ah[mt], bh);
                    mma16816(acc[mt][2 * np + 1], ah[mt], bh + 2);
                }
            }
        }

#pragma unroll
        for (int mt = 0; mt < 2; mt++) {
            float lo = -3.4e38f, hi = -3.4e38f;
#pragma unroll
            for (int nt = 0; nt < 4; nt++) {
                lo = fmaxf(lo, fmaxf(acc[mt][nt][0], acc[mt][nt][1]));
                hi = fmaxf(hi, fmaxf(acc[mt][nt][2], acc[mt][nt][3]));
            }
            lo = fmaxf(lo, __shfl_xor_sync(0xffffffffu, lo, 1));
            lo = fmaxf(lo, __shfl_xor_sync(0xffffffffu, lo, 2));
            hi = fmaxf(hi, __shfl_xor_sync(0xffffffffu, hi, 1));
            hi = fmaxf(hi, __shfl_xor_sync(0xffffffffu, hi, 2));
            if ((lane & 3) == 0) {
                int r = mbase + 16 * mt + (lane >> 2);
                red[r][wc] = lo;
                red[r + 8][wc] = hi;
            }
        }
        __syncthreads();
        if (tid < 128) {
            float v = fmaxf(fmaxf(red[tid][0], red[tid][1]),
                            fmaxf(red[tid][2], red[tid][3]));
            out[(size_t)(b * LL + tid) * OC + 21 + m] = tanhf(v);
        }
    }
}

// ================= branch: attnB (logits + softmax + att_lt + attentive mp) ======
// Dynamic smem layout (floats, total 27648 = 110592 B):
//   [0, 8256)      Z (64x129)       -- dead after Zh convert
//   [0, 12800)     attbuf (64x200)  -- overlays Z, live from phase 2
//   [12800, 16800) wsT (200x20)
//   [16800, 27648) halves region (21696 halves):
//       phase 1: ers_h 64x72 @h0, elts_h 128x72 @h4608
//       phase 2: Zh 64x136 @h0, ltsT_q 64x136 @h8704
__device__ __forceinline__ void attnB_block(
        const float* __restrict__ lt, const float* __restrict__ rt,
        const float* __restrict__ w_att, float* __restrict__ out,
        int b, int rh, float* sm) {
    float* Z = sm;
    float* attbuf = sm;
    float* wsT = sm + 12800;
    __half* hreg = (__half*)(sm + 16800);
    __half* ers_h = hreg;                // phase 1
    __half* elts_h = hreg + 4608;        // phase 1
    __half* Zh = hreg;                   // phase 2
    __half* ltsT = hreg + 8704;          // phase 2 (64 x 136 per substep)
    int tid = threadIdx.x, lane = tid & 31, wid = tid >> 5;

    // stage wsT + ers_h + elts_h
    for (int i = tid; i < DD * MPP; i += 512) {
        int d = i / MPP, m = i - d * MPP;
        wsT[d * MPP + m] = w_att[m * DD + d];
    }
    const float* ersrc = g_e_rt + ((size_t)b * LL + rh * 64) * ATTN;
    for (int i = tid; i < 64 * 36; i += 512) {
        int r = i / 36, kk = (i - r * 36) * 2;
        float v0 = (kk < 50) ? ersrc[r * 50 + kk] : 0.f;
        float v1 = (kk + 1 < 50) ? ersrc[r * 50 + kk + 1] : 0.f;
        *(__half2*)&ers_h[r * 72 + kk] = __float22half2_rn(make_float2(v0, v1));
    }
    const float* elsrc = g_e_lt + (size_t)b * LL * ATTN;
    for (int i = tid; i < 128 * 36; i += 512) {
        int r = i / 36, kk = (i - r * 36) * 2;
        float v0 = (kk < 50) ? elsrc[r * 50 + kk] : 0.f;
        float v1 = (kk + 1 < 50) ? elsrc[r * 50 + kk + 1] : 0.f;
        *(__half2*)&elts_h[r * 72 + kk] = __float22half2_rn(make_float2(v0, v1));
    }
    __syncthreads();

    uint32_t ers_b = smem_to_u32(ers_h);
    uint32_t elts_b = smem_to_u32(elts_h);
    uint32_t zh_b = smem_to_u32(Zh);
    uint32_t ltsT_b = smem_to_u32(ltsT);

    int wm = wid >> 2, wn = wid & 3;
    int mbase = wm * 16;
    int a_row = lane & 15;
    int a_col8 = (lane & 16) ? 8 : 0;
    int b_row = (lane & 7) + ((lane & 16) ? 8 : 0);
    int b_col8 = (lane & 8) ? 8 : 0;

    // phase 1: Z[64x128] = ers @ elts^T via mma (K=64)
    {
        int nbase = wn * 32;
        float acc[4][4];
#pragma unroll
        for (int t = 0; t < 4; t++)
#pragma unroll
            for (int q = 0; q < 4; q++) acc[t][q] = 0.f;
#pragma unroll
        for (int kt = 0; kt < 4; kt++) {
            uint32_t a[4];
            ldsm_x4(a, ers_b + ((mbase + a_row) * 72 + kt * 16 + a_col8) * 2);
#pragma unroll
            for (int np = 0; np < 2; np++) {
                uint32_t bh[4];
                ldsm_x4(bh, elts_b + ((nbase + np * 16 + b_row) * 72 + kt * 16 + b_col8) * 2);
                mma16816(acc[2 * np], a, bh);
                mma16816(acc[2 * np + 1], a, bh + 2);
            }
        }
        int rr = mbase + (lane >> 2);
#pragma unroll
        for (int t = 0; t < 4; t++) {
            int c = nbase + t * 8 + 2 * (lane & 3);
            Z[rr * 129 + c] = acc[t][0];
            Z[rr * 129 + c + 1] = acc[t][1];
            Z[(rr + 8) * 129 + c] = acc[t][2];
            Z[(rr + 8) * 129 + c + 1] = acc[t][3];
        }
    }
    __syncthreads();

    // softmax: 4 threads per row
    if (tid < 256) {
        int r = tid >> 2, h = tid & 3;
        float* zr = Z + r * 129 + h * 32;
        float mx = zr[0];
#pragma unroll 4
        for (int k = 1; k < 32; k++) mx = fmaxf(mx, zr[k]);
        mx = fmaxf(mx, __shfl_xor_sync(0xffffffffu, mx, 1));
        mx = fmaxf(mx, __shfl_xor_sync(0xffffffffu, mx, 2));
        float s = 0.f;
#pragma unroll 4
        for (int k = 0; k < 32; k++) {
            float e = expf(zr[k] - mx);
            zr[k] = e;
            s += e;
        }
        s += __shfl_xor_sync(0xffffffffu, s, 1);
        s += __shfl_xor_sync(0xffffffffu, s, 2);
        float inv = 1.f / s;
#pragma unroll 4
        for (int k = 0; k < 32; k++) zr[k] *= inv;
    }
    __syncthreads();

    // Zh convert [64 x 136] (overwrites ers_h region; Z row r half copied)
    {
        float zreg[8];
        int r = tid >> 3, kp = (tid & 7) * 16;  // 64 rows x 8 groups of 16
#pragma unroll
        for (int t = 0; t < 8; t++) zreg[t] = Z[r * 129 + kp + 2 * t];
        float zreg2[8];
#pragma unroll
        for (int t = 0; t < 8; t++) zreg2[t] = Z[r * 129 + kp + 2 * t + 1];
        __syncthreads();  // all reads of Z done before Zh overwrite? Zh != Z region (halves vs floats) -- no overlap, sync not needed for aliasing but keep order
#pragma unroll
        for (int t = 0; t < 8; t++)
            *(__half2*)&Zh[r * 136 + kp + 2 * t] =
                __float22half2_rn(make_float2(zreg[t], zreg2[t]));
    }
    __syncthreads();

    // phase 2: attbuf[64x200] = Z @ lt, 4 substeps of 64 d-cols
    const float* ltb = lt + (size_t)b * LL * DD;
    for (int s = 0; s < 4; s++) {
        // stage ltsT_q [64 x 136]: ltsT[d_local][l] = lt[l][s*64+d_local]
        for (int i = tid; i < 64 * 64; i += 512) {
            int dl = i & 63, lp = (i >> 6) * 2;
            int d = s * 64 + dl;
            float v0 = 0.f, v1 = 0.f;
            if (d < 200) {
                v0 = __ldg(ltb + lp * DD + d);
                v1 = __ldg(ltb + (lp + 1) * DD + d);
            }
            *(__half2*)&ltsT[dl * 136 + lp] = __float22half2_rn(make_float2(v0, v1));
        }
        __syncthreads();

        int nbase = wn * 16;
        float acc[2][4];
#pragma unroll
        for (int t = 0; t < 2; t++)
#pragma unroll
            for (int q = 0; q < 4; q++) acc[t][q] = 0.f;
#pragma unroll
        for (int kt = 0; kt < 8; kt++) {
            uint32_t a[4];
            ldsm_x4(a, zh_b + ((mbase + a_row) * 136 + kt * 16 + a_col8) * 2);
            uint32_t bh[4];
            ldsm_x4(bh, ltsT_b + ((nbase + b_row) * 136 + kt * 16 + b_col8) * 2);
            mma16816(acc[0], a, bh);
            mma16816(acc[1], a, bh + 2);
        }
        int rr = mbase + (lane >> 2);
#pragma unroll
        for (int t = 0; t < 2; t++) {
            int d = s * 64 + nbase + t * 8 + 2 * (lane & 3);
            if (d < 200) {
                attbuf[rr * DD + d] = acc[t][0];
                attbuf[rr * DD + d + 1] = acc[t][1];
                attbuf[(rr + 8) * DD + d] = acc[t][2];
                attbuf[(rr + 8) * DD + d + 1] = acc[t][3];
            }
        }
        __syncthreads();
    }

    // attentive mp-elementwise (cols [41,62)): 8 threads/row
    {
        int l = tid >> 3, q = tid & 7;
        int row = rh * 64 + l;
        const float* xp = attbuf + l * DD + q * 25;
        const float* yp = rt + (size_t)(b * LL + row) * DD + q * 25;
        float cos_acc = 0.f;
        ull macc[MPP / 2];
#pragma unroll
        for (int mm = 0; mm < MPP / 2; mm++) macc[mm] = 0ULL;
#pragma unroll
        for (int i = 0; i < 25; i++) {
            float p = xp[i] * __ldg(yp + i);
            cos_acc += p;
            ull pb = bcast2(p);
            const ull* wr = (const ull*)&wsT[(q * 25 + i) * MPP];
#pragma unroll
            for (int mm = 0; mm < MPP / 2; mm++) macc[mm] = ffma2u(pb, wr[mm], macc[mm]);
        }
        cos_acc += __shfl_xor_sync(0xffffffffu, cos_acc, 1);
        cos_acc += __shfl_xor_sync(0xffffffffu, cos_acc, 2);
        cos_acc += __shfl_xor_sync(0xffffffffu, cos_acc, 4);
#pragma unroll
        for (int mm = 0; mm < MPP / 2; mm++) {
            macc[mm] = addp2(macc[mm], __shfl_xor_sync(0xffffffffu, macc[mm], 1));
            macc[mm] = addp2(macc[mm], __shfl_xor_sync(0xffffffffu, macc[mm], 2));
            macc[mm] = addp2(macc[mm], __shfl_xor_sync(0xffffffffu, macc[mm], 4));
        }
        if (q == 0) {
            float* o = out + (size_t)(b * LL + row) * OC + 41;
            o[0] = tanhf(cos_acc);
#pragma unroll
            for (int mm = 0; mm < MPP / 2; mm++) {
                float2 f = unpack2(macc[mm]);
                o[1 + 2 * mm] = tanhf(f.x);
                o[2 + 2 * mm] = tanhf(f.y);
            }
        }
    }
}

// ================= branch: full match (cols [0,21)) =================
__device__ __forceinline__ void full_block(
        const float* __restrict__ lt, const float* __restrict__ fw,
        const float* __restrict__ bw, const float* __restrict__ wf,
        float* __restrict__ out, int b, float* sm) {
    float* hw = sm;
    int tid = threadIdx.x;
    for (int idx = tid; idx < (MPP + 1) * DD; idx += 512) {
        int mm = idx / DD, d = idx - mm * DD;
        float hv = (d < DD / 2) ? fw[b * (DD / 2) + d] : bw[b * (DD / 2) + d - DD / 2];
        hw[idx] = (mm == 0) ? hv : wf[(mm - 1) * DD + d] * hv;
    }
    __syncthreads();
    if (tid < 128) {
        const ull* row = (const ull*)(lt + (size_t)(b * LL + tid) * DD);
        ull acc[MPP + 1];
#pragma unroll
        for (int mm = 0; mm <= MPP; mm++) acc[mm] = 0ULL;
        for (int d2 = 0; d2 < DD / 2; d2++) {
            ull x = __ldg(row + d2);
#pragma unroll
            for (int mm = 0; mm <= MPP; mm++)
                acc[mm] = ffma2u(x, *(const ull*)&hw[mm * DD + 2 * d2], acc[mm]);
        }
        float* o = out + (size_t)(b * LL + tid) * OC;
#pragma unroll
        for (int mm = 0; mm <= MPP; mm++) {
            float2 f = unpack2(acc[mm]);
            o[mm] = tanhf(f.x + f.y);
        }
    }
}

// ======= branch: max-attentive argmax + its mp-elementwise (cols [62,83)) =======
__device__ __forceinline__ void maxatt_block(
        const float* __restrict__ lt, const float* __restrict__ rt,
        const float* __restrict__ w_maxatt, float* __restrict__ out,
        int b, int rh, float* sm) {
    float* As = sm;
    float* Bs = sm + 512;
    float* nlt = sm + 1536;
    float* redv = sm + 1664;
    int* redi = (int*)(sm + 2688);
    float* wsT = sm + 3712;
    int tid = threadIdx.x;
    int tx = tid & 15, ty = (tid >> 4) & 15;
    if (tid < 128) {
        const float4* p = (const float4*)(lt + (size_t)(b * LL + tid) * DD);
        float s = 0.f;
        for (int i = 0; i < DD / 4; i++) {
            float4 v = __ldg(p + i);
            s += v.x * v.x + v.y * v.y + v.z * v.z + v.w * v.w;
        }
        nlt[tid] = rsqrtf(fmaxf(s, 1e-6f));
    }
    for (int i = tid; i < DD * MPP; i += 512) {
        int d = i / MPP, m = i - d * MPP;
        wsT[d * MPP + m] = w_maxatt[m * DD + d];
    }
    int lrow = (tid >> 1) & 127, kq = tid & 1;
    int arow = (tid >> 1) & 63;
    const float4* bp = (const float4*)(lt + (size_t)(b * LL + lrow) * DD);
    const float4* ap = (const float4*)(rt + (size_t)(b * LL + rh * 64 + arow) * DD);
    ull acc[4][4];
#pragma unroll
    for (int i = 0; i < 4; i++)
#pragma unroll
        for (int j = 0; j < 4; j++) acc[i][j] = 0ULL;
    for (int kc = 0; kc < DD / 8; kc++) {
        if (tid < 256) {
            float4 bv = __ldg(bp + kc * 2 + kq);
            int kb = kq * 4;
            Bs[(kb + 0) * 128 + lrow] = bv.x;
            Bs[(kb + 1) * 128 + lrow] = bv.y;
            Bs[(kb + 2) * 128 + lrow] = bv.z;
            Bs[(kb + 3) * 128 + lrow] = bv.w;
            if (tid < 128) {
                float4 av = __ldg(ap + kc * 2 + kq);
                As[(kb + 0) * 64 + arow] = av.x;
                As[(kb + 1) * 64 + arow] = av.y;
                As[(kb + 2) * 64 + arow] = av.z;
                As[(kb + 3) * 64 + arow] = av.w;
            }
        }
        __syncthreads();
        if (tid < 256) {
#pragma unroll
            for (int k = 0; k < 8; k++) {
                ull a[4];
#pragma unroll
                for (int i = 0; i < 4; i++) a[i] = bcast2(As[k * 64 + ty + 16 * i]);
#pragma unroll
                for (int j = 0; j < 4; j++) {
                    ull bb = *(const ull*)&Bs[k * 128 + 2 * tx + 32 * j];
#pragma unroll
                    for (int i = 0; i < 4; i++) acc[i][j] = ffma2u(a[i], bb, acc[i][j]);
                }
            }
        }
        __syncthreads();
    }
    if (tid < 256) {
#pragma unroll
        for (int i = 0; i < 4; i++) {
            int r = ty + 16 * i;
            float best = -3.4e38f;
            int bi = 0;
#pragma unroll
            for (int j = 0; j < 4; j++) {
                int c = 2 * tx + 32 * j;
                float2 f = unpack2(acc[i][j]);
                float v0 = f.x * nlt[c];
                float v1 = f.y * nlt[c + 1];
                if (v0 > best) { best = v0; bi = c; }
                if (v1 > best) { best = v1; bi = c + 1; }
            }
            redv[r * 16 + tx] = best;
            redi[r * 16 + tx] = bi;
        }
    }
    __syncthreads();
    __shared__ int posbuf[64];
    if (tid < 64) {
        float best = redv[tid * 16];
        int bi = redi[tid * 16];
#pragma unroll
        for (int t = 1; t < 16; t++) {
            float v = redv[tid * 16 + t];
            int ii = redi[tid * 16 + t];
            if (v > best || (v == best && ii < bi)) { best = v; bi = ii; }
        }
        posbuf[tid] = bi;
    }
    __syncthreads();
    if (tid < 256) {
        int l = tid >> 2, q = tid & 3;
        int row = rh * 64 + l;
        const float2* xp = (const float2*)(rt + (size_t)(b * LL + row) * DD + q * 50);
        const float2* yp = (const float2*)(lt + (size_t)(b * LL + posbuf[l]) * DD + q * 50);
        float cos_acc = 0.f;
        ull macc[MPP / 2];
#pragma unroll
        for (int mm = 0; mm < MPP / 2; mm++) macc[mm] = 0ULL;
#pragma unroll
        for (int i = 0; i < 25; i++) {
            float2 x = __ldg(xp + i);
            float2 y = __ldg(yp + i);
            float p0 = x.x * y.x, p1 = x.y * y.y;
            cos_acc += p0 + p1;
            int d = q * 50 + 2 * i;
            ull pb0 = bcast2(p0), pb1 = bcast2(p1);
            const ull* w0 = (const ull*)&wsT[d * MPP];
            const ull* w1 = (const ull*)&wsT[(d + 1) * MPP];
#pragma unroll
            for (int mm = 0; mm < MPP / 2; mm++) {
                macc[mm] = ffma2u(pb0, w0[mm], macc[mm]);
                macc[mm] = ffma2u(pb1, w1[mm], macc[mm]);
            }
        }
        cos_acc += __shfl_xor_sync(0xffffffffu, cos_acc, 1);
        cos_acc += __shfl_xor_sync(0xffffffffu, cos_acc, 2);
#pragma unroll
        for (int mm = 0; mm < MPP / 2; mm++) {
            macc[mm] = addp2(macc[mm], __shfl_xor_sync(0xffffffffu, macc[mm], 1));
            macc[mm] = addp2(macc[mm], __shfl_xor_sync(0xffffffffu, macc[mm], 2));
        }
        if (q == 0) {
            float* o = out + (size_t)(b * LL + row) * OC + 62;
            o[0] = tanhf(cos_acc);
#pragma unroll
            for (int mm = 0; mm < MPP / 2; mm++) {
                float2 f = unpack2(macc[mm]);
                o[1 + 2 * mm] = tanhf(f.x);
                o[2 + 2 * mm] = tanhf(f.y);
            }
        }
    }
}

// ================= mega: everything except proj =================
#define GRID_MP (BB * (MPP / MGRP))     // 256
#define GRID_MEGA (GRID_MP + 2 * BB + 2 * BB + BB)   // 256+128+128+64 = 576

__global__ __launch_bounds__(512, 2) void mega(
        const float* __restrict__ lt, const float* __restrict__ rt,
        const float* __restrict__ fw, const float* __restrict__ bw,
        const float* __restrict__ w_full, const float* __restrict__ w_maxpool,
        const float* __restrict__ w_att, const float* __restrict__ w_maxatt,
        float* __restrict__ out) {
    extern __shared__ char smc[];
    __shared__ float red[128][4];
    int bx = blockIdx.x;
    if (bx < GRID_MP) {
        maxpool_block(lt, rt, w_maxpool, out, bx >> 2, (bx & 3) * MGRP, smc, red);
    } else if (bx < GRID_MP + 2 * BB) {
        int i = bx - GRID_MP;
        attnB_block(lt, rt, w_att, out, i >> 1, i & 1, (float*)smc);
    } else if (bx < GRID_MP + 4 * BB) {
        int i = bx - GRID_MP - 2 * BB;
        maxatt_block(lt, rt, w_maxatt, out, i >> 1, i & 1, (float*)smc);
    } else {
        full_block(lt, fw, bw, w_full, out, bx - GRID_MP - 4 * BB, (float*)smc);
    }
}

// ================= launch =================
extern "C" void kernel_launch(void* const* d_in, const int* in_sizes, int n_in,
                              void* d_out, int out_size) {
    const float* reps_lt = (const float*)d_in[0];
    const float* reps_rt = (const float*)d_in[1];
    const float* fw_h = (const float*)d_in[2];
    const float* bw_h = (const float*)d_in[3];
    const float* w_full = (const float*)d_in[4];
    const float* w_maxpool = (const float*)d_in[5];
    const float* w_att = (const float*)d_in[6];
    const float* w_maxatt = (const float*)d_in[7];
    const float* attn_w1 = (const float*)d_in[8];
    const float* attn_w2 = (const float*)d_in[9];
    const float* diag_w = (const float*)d_in[10];
    float* out = (float*)d_out;

    cudaFuncSetAttribute(projK, cudaFuncAttributeMaxDynamicSharedMemorySize, SMEM_PROJ);
    cudaFuncSetAttribute(mega, cudaFuncAttributeMaxDynamicSharedMemorySize, SMEM_MP);

    projK<<<dim3(BB, 2), 256, SMEM_PROJ>>>(reps_lt, reps_rt, attn_w1, attn_w2, diag_w);
    mega<<<GRID_MEGA, 512, SMEM_MP>>>(reps_lt, reps_rt, fw_h, bw_h, w_full,
                                      w_maxpool, w_att, w_maxatt, out);
}

// round 13
// speedup vs baseline: 1.1448x; 1.1448x over previous
#include <cuda_runtime.h>
#include <cuda_fp16.h>
#include <math.h>
#include <stdint.h>

#define BB 64
#define LL 128
#define DD 200
#define MPP 20
#define ATTN 50
#define OC 83

typedef unsigned long long ull;

// ---------------- scratch ----------------
__device__ __align__(16) float g_e_rt[BB * LL * ATTN];
__device__ __align__(16) float g_e_lt[BB * LL * ATTN];

// -------- packed fp32x2 helpers --------
__device__ __forceinline__ ull ffma2u(ull a, ull b, ull c) {
    ull d;
    asm("fma.rn.f32x2 %0, %1, %2, %3;" : "=l"(d) : "l"(a), "l"(b), "l"(c));
    return d;
}
__device__ __forceinline__ ull addp2(ull a, ull b) {
    ull d;
    asm("add.rn.f32x2 %0, %1, %2;" : "=l"(d) : "l"(a), "l"(b));
    return d;
}
__device__ __forceinline__ ull bcast2(float x) {
    ull r;
    asm("mov.b64 %0, {%1, %1};" : "=l"(r) : "f"(x));
    return r;
}
__device__ __forceinline__ float2 unpack2(ull v) {
    float2 f;
    asm("mov.b64 {%0, %1}, %2;" : "=f"(f.x), "=f"(f.y) : "l"(v));
    return f;
}

// -------- warp MMA helpers --------
__device__ __forceinline__ uint32_t smem_to_u32(const void* p) {
    uint32_t a;
    asm("{ .reg .u64 t; cvta.to.shared.u64 t, %1; cvt.u32.u64 %0, t; }" : "=r"(a) : "l"(p));
    return a;
}
__device__ __forceinline__ void ldsm_x4(uint32_t* r, uint32_t addr) {
    asm volatile("ldmatrix.sync.aligned.m8n8.x4.shared.b16 {%0,%1,%2,%3}, [%4];"
                 : "=r"(r[0]), "=r"(r[1]), "=r"(r[2]), "=r"(r[3]) : "r"(addr));
}
__device__ __forceinline__ void mma16816(float* c, const uint32_t* a, const uint32_t* b) {
    asm volatile(
        "mma.sync.aligned.m16n8k16.row.col.f32.f16.f16.f32 "
        "{%0,%1,%2,%3}, {%4,%5,%6,%7}, {%8,%9}, {%0,%1,%2,%3};"
        : "+f"(c[0]), "+f"(c[1]), "+f"(c[2]), "+f"(c[3])
        : "r"(a[0]), "r"(a[1]), "r"(a[2]), "r"(a[3]), "r"(b[0]), "r"(b[1]));
}

// ================= projK: attention projections (standalone, runs first) ======
#define SMEM_PROJ ((DD * ATTN + ATTN * 128) * 4)
__global__ __launch_bounds__(256) void projK(
        const float* __restrict__ lt, const float* __restrict__ rt,
        const float* __restrict__ w1, const float* __restrict__ w2,
        const float* __restrict__ diag) {
    extern __shared__ float sm[];
    float* ws = sm;
    float* pbuf = sm + DD * ATTN;
    int b = blockIdx.x, side = blockIdx.y, tid = threadIdx.x;
    const float* wsrc = side == 0 ? w1 : w2;
    for (int i = tid; i < DD * ATTN; i += 256) ws[i] = wsrc[i];
    __syncthreads();
    int l = tid & 127, dh = tid >> 7;
    const float* base = side == 0 ? rt : lt;
    const float4* row = (const float4*)(base + (size_t)(b * LL + l) * DD + dh * 100);
    ull acc[ATTN / 2];
#pragma unroll
    for (int a = 0; a < ATTN / 2; a++) acc[a] = 0ULL;
    for (int d4 = 0; d4 < 25; d4++) {
        float4 x = __ldg(row + d4);
        int d = dh * 100 + d4 * 4;
#pragma unroll
        for (int c = 0; c < 4; c++) {
            float xc = (c == 0) ? x.x : (c == 1) ? x.y : (c == 2) ? x.z : x.w;
            ull x2 = bcast2(xc);
            const ull* wr = (const ull*)&ws[(d + c) * ATTN];
#pragma unroll
            for (int a = 0; a < ATTN / 2; a++) acc[a] = ffma2u(x2, wr[a], acc[a]);
        }
    }
    if (dh == 1) {
#pragma unroll
        for (int a = 0; a < ATTN / 2; a++) {
            float2 f = unpack2(acc[a]);
            pbuf[(2 * a) * 128 + l] = f.x;
            pbuf[(2 * a + 1) * 128 + l] = f.y;
        }
    }
    __syncthreads();
    if (dh == 0) {
        float* e = (side == 0 ? g_e_rt : g_e_lt) + (size_t)(b * LL + l) * ATTN;
#pragma unroll
        for (int a = 0; a < ATTN / 2; a++) {
            float2 f = unpack2(acc[a]);
            float v0 = tanhf(f.x + pbuf[(2 * a) * 128 + l]);
            float v1 = tanhf(f.y + pbuf[(2 * a + 1) * 128 + l]);
            if (side == 0) {
                v0 *= __ldg(diag + 2 * a);
                v1 *= __ldg(diag + 2 * a + 1);
            }
            e[2 * a] = v0;
            e[2 * a + 1] = v1;
        }
    }
}

// ======================================================================
// maxpool: CTA = (b, m-group of 5). Plain fp16 A x B (single pass).
// ======================================================================
#define STRD 216
#define TILE_B (LL * STRD * 2)
#define OFF_A 0
#define OFF_B (TILE_B)
#define SMEM_MP (2 * TILE_B)            // 110592
#define MGRP 5

__device__ __forceinline__ void maxpool_block(
        const float* __restrict__ lt, const float* __restrict__ rt,
        const float* __restrict__ w, float* __restrict__ out,
        int b, int mg0, char* smc, float (*red)[4]) {
    uint32_t sbase = smem_to_u32(smc);
    int tid = threadIdx.x, lane = tid & 31, wid = tid >> 5;

    for (int i = tid; i < 128 * 4; i += 512) {
        int r = i >> 2, c = i & 3;
        int off = (r * STRD + 200 + 2 * c) * 2;
        *(uint32_t*)(smc + OFF_A + off) = 0;
        *(uint32_t*)(smc + OFF_B + off) = 0;
    }
    const float* ltb = lt + (size_t)b * LL * DD;
    const float* rtb = rt + (size_t)b * LL * DD;
    for (int i = tid; i < LL * 100; i += 512) {
        int r = i / 100, k = (i - r * 100) * 2;
        float2 x = *(const float2*)(ltb + r * DD + k);
        __half2 h2 = __float22half2_rn(x);
        *(uint32_t*)(smc + OFF_A + (r * STRD + k) * 2) = *(uint32_t*)&h2;
    }

    int mbase = (wid >> 2) * 32, nbase = (wid & 3) * 32;
    int a_row = lane & 15;
    int a_col8 = (lane & 16) ? 8 : 0;
    int b_row = (lane & 7) + ((lane & 16) ? 8 : 0);
    int b_col8 = (lane & 8) ? 8 : 0;
    int wc = wid & 3;

#pragma unroll 1
    for (int mg = 0; mg < MGRP; mg++) {
        int m = mg0 + mg;
        const float* wm = w + (size_t)m * DD;
        for (int i = tid; i < LL * 100; i += 512) {
            int r = i / 100, k = (i - r * 100) * 2;
            float2 xb = *(const float2*)(rtb + r * DD + k);
            float2 ww = *(const float2*)(wm + k);
            __half2 h2 = __float22half2_rn(make_float2(xb.x * ww.x, xb.y * ww.y));
            *(uint32_t*)(smc + OFF_B + (r * STRD + k) * 2) = *(uint32_t*)&h2;
        }
        __syncthreads();

        float acc[2][4][4];
#pragma unroll
        for (int mt = 0; mt < 2; mt++)
#pragma unroll
            for (int nt = 0; nt < 4; nt++)
#pragma unroll
                for (int q = 0; q < 4; q++) acc[mt][nt][q] = 0.f;

#pragma unroll 1
        for (int kg = 0; kg < 13; kg++) {
            int kc = kg * 16;
            uint32_t ah[2][4];
#pragma unroll
            for (int mt = 0; mt < 2; mt++) {
                uint32_t row = mbase + 16 * mt + a_row;
                ldsm_x4(ah[mt], sbase + OFF_A + (row * STRD + kc + a_col8) * 2);
            }
#pragma unroll
            for (int np = 0; np < 2; np++) {
                uint32_t row = nbase + np * 16 + b_row;
                uint32_t bh[4];
                ldsm_x4(bh, sbase + OFF_B + (row * STRD + kc + b_col8) * 2);
#pragma unroll
                for (int mt = 0; mt < 2; mt++) {
                    mma16816(acc[mt][2 * np], ah[mt], bh);
                    mma16816(acc[mt][2 * np + 1], ah[mt], bh + 2);
                }
            }
        }

#pragma unroll
        for (int mt = 0; mt < 2; mt++) {
            float lo = -3.4e38f, hi = -3.4e38f;
#pragma unroll
            for (int nt = 0; nt < 4; nt++) {
                lo = fmaxf(lo, fmaxf(acc[mt][nt][0], acc[mt][nt][1]));
                hi = fmaxf(hi, fmaxf(acc[mt][nt][2], acc[mt][nt][3]));
            }
            lo = fmaxf(lo, __shfl_xor_sync(0xffffffffu, lo, 1));
            lo = fmaxf(lo, __shfl_xor_sync(0xffffffffu, lo, 2));
            hi = fmaxf(hi, __shfl_xor_sync(0xffffffffu, hi, 1));
            hi = fmaxf(hi, __shfl_xor_sync(0xffffffffu, hi, 2));
            if ((lane & 3) == 0) {
                int r = mbase + 16 * mt + (lane >> 2);
                red[r][wc] = lo;
                red[r + 8][wc] = hi;
            }
        }
        __syncthreads();
        if (tid < 128) {
            float v = fmaxf(fmaxf(red[tid][0], red[tid][1]),
                            fmaxf(red[tid][2], red[tid][3]));
            out[(size_t)(b * LL + tid) * OC + 21 + m] = tanhf(v);
        }
    }
}

// ================= branch: attnB (logits + softmax + att_lt + attentive mp) ======
__device__ __forceinline__ void attnB_block(
        const float* __restrict__ lt, const float* __restrict__ rt,
        const float* __restrict__ w_att, float* __restrict__ out,
        int b, int rh, float* sm) {
    float* Z = sm;
    float* attbuf = sm;
    float* wsT = sm + 12800;
    __half* hreg = (__half*)(sm + 16800);
    __half* ers_h = hreg;
    __half* elts_h = hreg + 4608;
    __half* Zh = hreg;
    __half* ltsT = hreg + 8704;
    int tid = threadIdx.x, lane = tid & 31, wid = tid >> 5;

    for (int i = tid; i < DD * MPP; i += 512) {
        int d = i / MPP, m = i - d * MPP;
        wsT[d * MPP + m] = w_att[m * DD + d];
    }
    const float* ersrc = g_e_rt + ((size_t)b * LL + rh * 64) * ATTN;
    for (int i = tid; i < 64 * 36; i += 512) {
        int r = i / 36, kk = (i - r * 36) * 2;
        float v0 = (kk < 50) ? ersrc[r * 50 + kk] : 0.f;
        float v1 = (kk + 1 < 50) ? ersrc[r * 50 + kk + 1] : 0.f;
        *(__half2*)&ers_h[r * 72 + kk] = __float22half2_rn(make_float2(v0, v1));
    }
    const float* elsrc = g_e_lt + (size_t)b * LL * ATTN;
    for (int i = tid; i < 128 * 36; i += 512) {
        int r = i / 36, kk = (i - r * 36) * 2;
        float v0 = (kk < 50) ? elsrc[r * 50 + kk] : 0.f;
        float v1 = (kk + 1 < 50) ? elsrc[r * 50 + kk + 1] : 0.f;
        *(__half2*)&elts_h[r * 72 + kk] = __float22half2_rn(make_float2(v0, v1));
    }
    __syncthreads();

    uint32_t ers_b = smem_to_u32(ers_h);
    uint32_t elts_b = smem_to_u32(elts_h);
    uint32_t zh_b = smem_to_u32(Zh);
    uint32_t ltsT_b = smem_to_u32(ltsT);

    int wm = wid >> 2, wn = wid & 3;
    int mbase = wm * 16;
    int a_row = lane & 15;
    int a_col8 = (lane & 16) ? 8 : 0;
    int b_row = (lane & 7) + ((lane & 16) ? 8 : 0);
    int b_col8 = (lane & 8) ? 8 : 0;

    // phase 1: Z[64x128] = ers @ elts^T (K=64)
    {
        int nbase = wn * 32;
        float acc[4][4];
#pragma unroll
        for (int t = 0; t < 4; t++)
#pragma unroll
            for (int q = 0; q < 4; q++) acc[t][q] = 0.f;
#pragma unroll
        for (int kt = 0; kt < 4; kt++) {
            uint32_t a[4];
            ldsm_x4(a, ers_b + ((mbase + a_row) * 72 + kt * 16 + a_col8) * 2);
#pragma unroll
            for (int np = 0; np < 2; np++) {
                uint32_t bh[4];
                ldsm_x4(bh, elts_b + ((nbase + np * 16 + b_row) * 72 + kt * 16 + b_col8) * 2);
                mma16816(acc[2 * np], a, bh);
                mma16816(acc[2 * np + 1], a, bh + 2);
            }
        }
        int rr = mbase + (lane >> 2);
#pragma unroll
        for (int t = 0; t < 4; t++) {
            int c = nbase + t * 8 + 2 * (lane & 3);
            Z[rr * 129 + c] = acc[t][0];
            Z[rr * 129 + c + 1] = acc[t][1];
            Z[(rr + 8) * 129 + c] = acc[t][2];
            Z[(rr + 8) * 129 + c + 1] = acc[t][3];
        }
    }
    __syncthreads();

    if (tid < 256) {
        int r = tid >> 2, h = tid & 3;
        float* zr = Z + r * 129 + h * 32;
        float mx = zr[0];
#pragma unroll 4
        for (int k = 1; k < 32; k++) mx = fmaxf(mx, zr[k]);
        mx = fmaxf(mx, __shfl_xor_sync(0xffffffffu, mx, 1));
        mx = fmaxf(mx, __shfl_xor_sync(0xffffffffu, mx, 2));
        float s = 0.f;
#pragma unroll 4
        for (int k = 0; k < 32; k++) {
            float e = expf(zr[k] - mx);
            zr[k] = e;
            s += e;
        }
        s += __shfl_xor_sync(0xffffffffu, s, 1);
        s += __shfl_xor_sync(0xffffffffu, s, 2);
        float inv = 1.f / s;
#pragma unroll 4
        for (int k = 0; k < 32; k++) zr[k] *= inv;
    }
    __syncthreads();

    {
        float zreg[8];
        int r = tid >> 3, kp = (tid & 7) * 16;
#pragma unroll
        for (int t = 0; t < 8; t++) zreg[t] = Z[r * 129 + kp + 2 * t];
        float zreg2[8];
#pragma unroll
        for (int t = 0; t < 8; t++) zreg2[t] = Z[r * 129 + kp + 2 * t + 1];
        __syncthreads();
#pragma unroll
        for (int t = 0; t < 8; t++)
            *(__half2*)&Zh[r * 136 + kp + 2 * t] =
                __float22half2_rn(make_float2(zreg[t], zreg2[t]));
    }
    __syncthreads();

    const float* ltb = lt + (size_t)b * LL * DD;
    for (int s = 0; s < 4; s++) {
        for (int i = tid; i < 64 * 64; i += 512) {
            int dl = i & 63, lp = (i >> 6) * 2;
            int d = s * 64 + dl;
            float v0 = 0.f, v1 = 0.f;
            if (d < 200) {
                v0 = __ldg(ltb + lp * DD + d);
                v1 = __ldg(ltb + (lp + 1) * DD + d);
            }
            *(__half2*)&ltsT[dl * 136 + lp] = __float22half2_rn(make_float2(v0, v1));
        }
        __syncthreads();

        int nbase = wn * 16;
        float acc[2][4];
#pragma unroll
        for (int t = 0; t < 2; t++)
#pragma unroll
            for (int q = 0; q < 4; q++) acc[t][q] = 0.f;
#pragma unroll
        for (int kt = 0; kt < 8; kt++) {
            uint32_t a[4];
            ldsm_x4(a, zh_b + ((mbase + a_row) * 136 + kt * 16 + a_col8) * 2);
            uint32_t bh[4];
            ldsm_x4(bh, ltsT_b + ((nbase + b_row) * 136 + kt * 16 + b_col8) * 2);
            mma16816(acc[0], a, bh);
            mma16816(acc[1], a, bh + 2);
        }
        int rr = mbase + (lane >> 2);
#pragma unroll
        for (int t = 0; t < 2; t++) {
            int d = s * 64 + nbase + t * 8 + 2 * (lane & 3);
            if (d < 200) {
                attbuf[rr * DD + d] = acc[t][0];
                attbuf[rr * DD + d + 1] = acc[t][1];
                attbuf[(rr + 8) * DD + d] = acc[t][2];
                attbuf[(rr + 8) * DD + d + 1] = acc[t][3];
            }
        }
        __syncthreads();
    }

    {
        int l = tid >> 3, q = tid & 7;
        int row = rh * 64 + l;
        const float* xp = attbuf + l * DD + q * 25;
        const float* yp = rt + (size_t)(b * LL + row) * DD + q * 25;
        float cos_acc = 0.f;
        ull macc[MPP / 2];
#pragma unroll
        for (int mm = 0; mm < MPP / 2; mm++) macc[mm] = 0ULL;
#pragma unroll
        for (int i = 0; i < 25; i++) {
            float p = xp[i] * __ldg(yp + i);
            cos_acc += p;
            ull pb = bcast2(p);
            const ull* wr = (const ull*)&wsT[(q * 25 + i) * MPP];
#pragma unroll
            for (int mm = 0; mm < MPP / 2; mm++) macc[mm] = ffma2u(pb, wr[mm], macc[mm]);
        }
        cos_acc += __shfl_xor_sync(0xffffffffu, cos_acc, 1);
        cos_acc += __shfl_xor_sync(0xffffffffu, cos_acc, 2);
        cos_acc += __shfl_xor_sync(0xffffffffu, cos_acc, 4);
#pragma unroll
        for (int mm = 0; mm < MPP / 2; mm++) {
            macc[mm] = addp2(macc[mm], __shfl_xor_sync(0xffffffffu, macc[mm], 1));
            macc[mm] = addp2(macc[mm], __shfl_xor_sync(0xffffffffu, macc[mm], 2));
            macc[mm] = addp2(macc[mm], __shfl_xor_sync(0xffffffffu, macc[mm], 4));
        }
        if (q == 0) {
            float* o = out + (size_t)(b * LL + row) * OC + 41;
            o[0] = tanhf(cos_acc);
#pragma unroll
            for (int mm = 0; mm < MPP / 2; mm++) {
                float2 f = unpack2(macc[mm]);
                o[1 + 2 * mm] = tanhf(f.x);
                o[2 + 2 * mm] = tanhf(f.y);
            }
        }
    }
}

// ================= branch: full match (cols [0,21)) =================
__device__ __forceinline__ void full_block(
        const float* __restrict__ lt, const float* __restrict__ fw,
        const float* __restrict__ bw, const float* __restrict__ wf,
        float* __restrict__ out, int b, float* sm) {
    float* hw = sm;
    int tid = threadIdx.x;
    for (int idx = tid; idx < (MPP + 1) * DD; idx += 512) {
        int mm = idx / DD, d = idx - mm * DD;
        float hv = (d < DD / 2) ? fw[b * (DD / 2) + d] : bw[b * (DD / 2) + d - DD / 2];
        hw[idx] = (mm == 0) ? hv : wf[(mm - 1) * DD + d] * hv;
    }
    __syncthreads();
    if (tid < 128) {
        const ull* row = (const ull*)(lt + (size_t)(b * LL + tid) * DD);
        ull acc[MPP + 1];
#pragma unroll
        for (int mm = 0; mm <= MPP; mm++) acc[mm] = 0ULL;
        for (int d2 = 0; d2 < DD / 2; d2++) {
            ull x = __ldg(row + d2);
#pragma unroll
            for (int mm = 0; mm <= MPP; mm++)
                acc[mm] = ffma2u(x, *(const ull*)&hw[mm * DD + 2 * d2], acc[mm]);
        }
        float* o = out + (size_t)(b * LL + tid) * OC;
#pragma unroll
        for (int mm = 0; mm <= MPP; mm++) {
            float2 f = unpack2(acc[mm]);
            o[mm] = tanhf(f.x + f.y);
        }
    }
}

// ======= branch: max-attentive via fp16 mma + exact top-candidate rescore =======
// smem layout (bytes): A(rt half) fp16 [64x216] @0 (27648) | B(lt) fp16 [128x216]
//   @27648 (55296) | nlt[128]f @82944 | wmax[64*4]f @83456 | rowmax[64]f @84480 |
//   cnt[64]i @84736 | cand[64*8]i @84992 | pos[64]i @87040 | wsT[200*20]f @87296
#define MA_MARGIN 0.02f
__device__ __forceinline__ void maxatt_block(
        const float* __restrict__ lt, const float* __restrict__ rt,
        const float* __restrict__ w_maxatt, float* __restrict__ out,
        int b, int rh, char* smc) {
    uint32_t sbase = smem_to_u32(smc);
    float* nlt = (float*)(smc + 82944);
    float* wmax = (float*)(smc + 83456);
    float* rowmax = (float*)(smc + 84480);
    int* cnt = (int*)(smc + 84736);
    int* cand = (int*)(smc + 84992);
    int* pos = (int*)(smc + 87040);
    float* wsT = (float*)(smc + 87296);
    int tid = threadIdx.x, lane = tid & 31, wid = tid >> 5;

    // nlt (fp32, exact)
    if (tid < 128) {
        const float4* p = (const float4*)(lt + (size_t)(b * LL + tid) * DD);
        float s = 0.f;
        for (int i = 0; i < DD / 4; i++) {
            float4 v = __ldg(p + i);
            s += v.x * v.x + v.y * v.y + v.z * v.z + v.w * v.w;
        }
        nlt[tid] = rsqrtf(fmaxf(s, 1e-6f));
    }
    if (tid < 64) cnt[tid] = 0;
    // wsT
    for (int i = tid; i < DD * MPP; i += 512) {
        int d = i / MPP, m = i - d * MPP;
        wsT[d * MPP + m] = w_maxatt[m * DD + d];
    }
    // zero pads + convert A (rt half) and B (lt) to fp16
    for (int i = tid; i < (64 + 128) * 4; i += 512) {
        int rr = i >> 2, c = i & 3;
        if (rr < 64)
            *(uint32_t*)(smc + (rr * STRD + 200 + 2 * c) * 2) = 0;
        else
            *(uint32_t*)(smc + 27648 + ((rr - 64) * STRD + 200 + 2 * c) * 2) = 0;
    }
    const float* rtb = rt + ((size_t)b * LL + rh * 64) * DD;
    for (int i = tid; i < 64 * 100; i += 512) {
        int r = i / 100, k = (i - r * 100) * 2;
        float2 x = *(const float2*)(rtb + r * DD + k);
        __half2 h2 = __float22half2_rn(x);
        *(uint32_t*)(smc + (r * STRD + k) * 2) = *(uint32_t*)&h2;
    }
    const float* ltb = lt + (size_t)b * LL * DD;
    for (int i = tid; i < 128 * 100; i += 512) {
        int r = i / 100, k = (i - r * 100) * 2;
        float2 x = *(const float2*)(ltb + r * DD + k);
        __half2 h2 = __float22half2_rn(x);
        *(uint32_t*)(smc + 27648 + (r * STRD + k) * 2) = *(uint32_t*)&h2;
    }
    __syncthreads();

    // mma: NUM[64x128] = A @ B^T ; warp = 16 rows x 32 cols
    int wm = wid >> 2, wn = wid & 3;
    int mbase = wm * 16, nbase = wn * 32;
    int a_row = lane & 15;
    int a_col8 = (lane & 16) ? 8 : 0;
    int b_row = (lane & 7) + ((lane & 16) ? 8 : 0);
    int b_col8 = (lane & 8) ? 8 : 0;
    float acc[4][4];
#pragma unroll
    for (int t = 0; t < 4; t++)
#pragma unroll
        for (int q = 0; q < 4; q++) acc[t][q] = 0.f;
#pragma unroll 1
    for (int kg = 0; kg < 13; kg++) {
        int kc = kg * 16;
        uint32_t a[4];
        ldsm_x4(a, sbase + ((mbase + a_row) * STRD + kc + a_col8) * 2);
#pragma unroll
        for (int np = 0; np < 2; np++) {
            uint32_t bh[4];
            ldsm_x4(bh, sbase + 27648 + ((nbase + np * 16 + b_row) * STRD + kc + b_col8) * 2);
            mma16816(acc[2 * np], a, bh);
            mma16816(acc[2 * np + 1], a, bh + 2);
        }
    }
    // scale by nlt; row maxes
    int rr = mbase + (lane >> 2);
    float vlo = -3.4e38f, vhi = -3.4e38f;
#pragma unroll
    for (int t = 0; t < 4; t++) {
        int c = nbase + t * 8 + 2 * (lane & 3);
        acc[t][0] *= nlt[c];
        acc[t][1] *= nlt[c + 1];
        acc[t][2] *= nlt[c];
        acc[t][3] *= nlt[c + 1];
        vlo = fmaxf(vlo, fmaxf(acc[t][0], acc[t][1]));
        vhi = fmaxf(vhi, fmaxf(acc[t][2], acc[t][3]));
    }
    vlo = fmaxf(vlo, __shfl_xor_sync(0xffffffffu, vlo, 1));
    vlo = fmaxf(vlo, __shfl_xor_sync(0xffffffffu, vlo, 2));
    vhi = fmaxf(vhi, __shfl_xor_sync(0xffffffffu, vhi, 1));
    vhi = fmaxf(vhi, __shfl_xor_sync(0xffffffffu, vhi, 2));
    if ((lane & 3) == 0) {
        wmax[rr * 4 + wn] = vlo;
        wmax[(rr + 8) * 4 + wn] = vhi;
    }
    __syncthreads();
    if (tid < 64)
        rowmax[tid] = fmaxf(fmaxf(wmax[tid * 4], wmax[tid * 4 + 1]),
                            fmaxf(wmax[tid * 4 + 2], wmax[tid * 4 + 3]));
    __syncthreads();
    // collect candidates within margin
    {
        float thr_lo = rowmax[rr] - MA_MARGIN;
        float thr_hi = rowmax[rr + 8] - MA_MARGIN;
#pragma unroll
        for (int t = 0; t < 4; t++) {
            int c = nbase + t * 8 + 2 * (lane & 3);
            if (acc[t][0] >= thr_lo) {
                int s = atomicAdd(&cnt[rr], 1);
                if (s < 8) cand[rr * 8 + s] = c;
            }
            if (acc[t][1] >= thr_lo) {
                int s = atomicAdd(&cnt[rr], 1);
                if (s < 8) cand[rr * 8 + s] = c + 1;
            }
            if (acc[t][2] >= thr_hi) {
                int s = atomicAdd(&cnt[rr + 8], 1);
                if (s < 8) cand[(rr + 8) * 8 + s] = c;
            }
            if (acc[t][3] >= thr_hi) {
                int s = atomicAdd(&cnt[rr + 8], 1);
                if (s < 8) cand[(rr + 8) * 8 + s] = c + 1;
            }
        }
    }
    __syncthreads();
    // exact rescore: warp wid handles rows wid*4 .. wid*4+3
    for (int rq = 0; rq < 4; rq++) {
        int r = wid * 4 + rq;
        int n = min(cnt[r], 8);
        const float* rtrow = rt + ((size_t)b * LL + rh * 64 + r) * DD;
        float best = -3.4e38f;
        int bi = 1 << 30;
        for (int j = 0; j < n; j++) {
            int c = cand[r * 8 + j];
            const float* ltrow = lt + ((size_t)b * LL + c) * DD;
            float s = 0.f;
            for (int k = lane; k < DD; k += 32) s += rtrow[k] * ltrow[k];
            s += __shfl_xor_sync(0xffffffffu, s, 16);
            s += __shfl_xor_sync(0xffffffffu, s, 8);
            s += __shfl_xor_sync(0xffffffffu, s, 4);
            s += __shfl_xor_sync(0xffffffffu, s, 2);
            s += __shfl_xor_sync(0xffffffffu, s, 1);
            float rel = s * nlt[c];
            if (rel > best || (rel == best && c < bi)) {
                best = rel;
                bi = c;
            }
        }
        if (lane == 0) pos[r] = bi;
    }
    __syncthreads();
    // mp-elementwise (cols [62,83)): X = rt row, Y = lt[pos]
    if (tid < 256) {
        int l = tid >> 2, q = tid & 3;
        int row = rh * 64 + l;
        const float2* xp = (const float2*)(rt + (size_t)(b * LL + row) * DD + q * 50);
        const float2* yp = (const float2*)(lt + (size_t)(b * LL + pos[l]) * DD + q * 50);
        float cos_acc = 0.f;
        ull macc[MPP / 2];
#pragma unroll
        for (int mm = 0; mm < MPP / 2; mm++) macc[mm] = 0ULL;
#pragma unroll
        for (int i = 0; i < 25; i++) {
            float2 x = __ldg(xp + i);
            float2 y = __ldg(yp + i);
            float p0 = x.x * y.x, p1 = x.y * y.y;
            cos_acc += p0 + p1;
            int d = q * 50 + 2 * i;
            ull pb0 = bcast2(p0), pb1 = bcast2(p1);
            const ull* w0 = (const ull*)&wsT[d * MPP];
            const ull* w1 = (const ull*)&wsT[(d + 1) * MPP];
#pragma unroll
            for (int mm = 0; mm < MPP / 2; mm++) {
                macc[mm] = ffma2u(pb0, w0[mm], macc[mm]);
                macc[mm] = ffma2u(pb1, w1[mm], macc[mm]);
            }
        }
        cos_acc += __shfl_xor_sync(0xffffffffu, cos_acc, 1);
        cos_acc += __shfl_xor_sync(0xffffffffu, cos_acc, 2);
#pragma unroll
        for (int mm = 0; mm < MPP / 2; mm++) {
            macc[mm] = addp2(macc[mm], __shfl_xor_sync(0xffffffffu, macc[mm], 1));
            macc[mm] = addp2(macc[mm], __shfl_xor_sync(0xffffffffu, macc[mm], 2));
        }
        if (q == 0) {
            float* o = out + (size_t)(b * LL + row) * OC + 62;
            o[0] = tanhf(cos_acc);
#pragma unroll
            for (int mm = 0; mm < MPP / 2; mm++) {
                float2 f = unpack2(macc[mm]);
                o[1 + 2 * mm] = tanhf(f.x);
                o[2 + 2 * mm] = tanhf(f.y);
            }
        }
    }
}

// ================= mega: everything except proj =================
#define GRID_MP (BB * (MPP / MGRP))     // 256
#define GRID_MEGA (GRID_MP + 2 * BB + 2 * BB + BB)   // 576

__global__ __launch_bounds__(512, 2) void mega(
        const float* __restrict__ lt, const float* __restrict__ rt,
        const float* __restrict__ fw, const float* __restrict__ bw,
        const float* __restrict__ w_full, const float* __restrict__ w_maxpool,
        const float* __restrict__ w_att, const float* __restrict__ w_maxatt,
        float* __restrict__ out) {
    extern __shared__ char smc[];
    __shared__ float red[128][4];
    int bx = blockIdx.x;
    if (bx < GRID_MP) {
        maxpool_block(lt, rt, w_maxpool, out, bx >> 2, (bx & 3) * MGRP, smc, red);
    } else if (bx < GRID_MP + 2 * BB) {
        int i = bx - GRID_MP;
        maxatt_block(lt, rt, w_maxatt, out, i >> 1, i & 1, smc);
    } else if (bx < GRID_MP + 4 * BB) {
        int i = bx - GRID_MP - 2 * BB;
        attnB_block(lt, rt, w_att, out, i >> 1, i & 1, (float*)smc);
    } else {
        full_block(lt, fw, bw, w_full, out, bx - GRID_MP - 4 * BB, (float*)smc);
    }
}

// ================= launch =================
extern "C" void kernel_launch(void* const* d_in, const int* in_sizes, int n_in,
                              void* d_out, int out_size) {
    const float* reps_lt = (const float*)d_in[0];
    const float* reps_rt = (const float*)d_in[1];
    const float* fw_h = (const float*)d_in[2];
    const float* bw_h = (const float*)d_in[3];
    const float* w_full = (const float*)d_in[4];
    const float* w_maxpool = (const float*)d_in[5];
    const float* w_att = (const float*)d_in[6];
    const float* w_maxatt = (const float*)d_in[7];
    const float* attn_w1 = (const float*)d_in[8];
    const float* attn_w2 = (const float*)d_in[9];
    const float* diag_w = (const float*)d_in[10];
    float* out = (float*)d_out;

    cudaFuncSetAttribute(projK, cudaFuncAttributeMaxDynamicSharedMemorySize, SMEM_PROJ);
    cudaFuncSetAttribute(mega, cudaFuncAttributeMaxDynamicSharedMemorySize, SMEM_MP);

    projK<<<dim3(BB, 2), 256, SMEM_PROJ>>>(reps_lt, reps_rt, attn_w1, attn_w2, diag_w);
    mega<<<GRID_MEGA, 512, SMEM_MP>>>(reps_lt, reps_rt, fw_h, bw_h, w_full,
                                      w_maxpool, w_att, w_maxatt, out);
}

// round 14
// speedup vs baseline: 1.3076x; 1.1422x over previous
#include <cuda_runtime.h>
#include <cuda_fp16.h>
#include <math.h>
#include <stdint.h>

#define BB 64
#define LL 128
#define DD 200
#define MPP 20
#define ATTN 50
#define OC 83

typedef unsigned long long ull;

// ---------------- scratch ----------------
__device__ __align__(16) float g_e_rt[BB * LL * ATTN];
__device__ __align__(16) float g_e_lt[BB * LL * ATTN];

// -------- packed fp32x2 helpers --------
__device__ __forceinline__ ull ffma2u(ull a, ull b, ull c) {
    ull d;
    asm("fma.rn.f32x2 %0, %1, %2, %3;" : "=l"(d) : "l"(a), "l"(b), "l"(c));
    return d;
}
__device__ __forceinline__ ull addp2(ull a, ull b) {
    ull d;
    asm("add.rn.f32x2 %0, %1, %2;" : "=l"(d) : "l"(a), "l"(b));
    return d;
}
__device__ __forceinline__ ull bcast2(float x) {
    ull r;
    asm("mov.b64 %0, {%1, %1};" : "=l"(r) : "f"(x));
    return r;
}
__device__ __forceinline__ float2 unpack2(ull v) {
    float2 f;
    asm("mov.b64 {%0, %1}, %2;" : "=f"(f.x), "=f"(f.y) : "l"(v));
    return f;
}

// -------- warp MMA helpers --------
__device__ __forceinline__ uint32_t smem_to_u32(const void* p) {
    uint32_t a;
    asm("{ .reg .u64 t; cvta.to.shared.u64 t, %1; cvt.u32.u64 %0, t; }" : "=r"(a) : "l"(p));
    return a;
}
__device__ __forceinline__ void ldsm_x4(uint32_t* r, uint32_t addr) {
    asm volatile("ldmatrix.sync.aligned.m8n8.x4.shared.b16 {%0,%1,%2,%3}, [%4];"
                 : "=r"(r[0]), "=r"(r[1]), "=r"(r[2]), "=r"(r[3]) : "r"(addr));
}
__device__ __forceinline__ void mma16816(float* c, const uint32_t* a, const uint32_t* b) {
    asm volatile(
        "mma.sync.aligned.m16n8k16.row.col.f32.f16.f16.f32 "
        "{%0,%1,%2,%3}, {%4,%5,%6,%7}, {%8,%9}, {%0,%1,%2,%3};"
        : "+f"(c[0]), "+f"(c[1]), "+f"(c[2]), "+f"(c[3])
        : "r"(a[0]), "r"(a[1]), "r"(a[2]), "r"(a[3]), "r"(b[0]), "r"(b[1]));
}

// ================= projK: attention projections (standalone, runs first) ======
#define SMEM_PROJ ((DD * ATTN + ATTN * 128) * 4)
__global__ __launch_bounds__(256) void projK(
        const float* __restrict__ lt, const float* __restrict__ rt,
        const float* __restrict__ w1, const float* __restrict__ w2,
        const float* __restrict__ diag) {
    extern __shared__ float sm[];
    float* ws = sm;
    float* pbuf = sm + DD * ATTN;
    int b = blockIdx.x, side = blockIdx.y, tid = threadIdx.x;
    const float* wsrc = side == 0 ? w1 : w2;
    for (int i = tid; i < DD * ATTN; i += 256) ws[i] = wsrc[i];
    __syncthreads();
    int l = tid & 127, dh = tid >> 7;
    const float* base = side == 0 ? rt : lt;
    const float4* row = (const float4*)(base + (size_t)(b * LL + l) * DD + dh * 100);
    ull acc[ATTN / 2];
#pragma unroll
    for (int a = 0; a < ATTN / 2; a++) acc[a] = 0ULL;
    for (int d4 = 0; d4 < 25; d4++) {
        float4 x = __ldg(row + d4);
        int d = dh * 100 + d4 * 4;
#pragma unroll
        for (int c = 0; c < 4; c++) {
            float xc = (c == 0) ? x.x : (c == 1) ? x.y : (c == 2) ? x.z : x.w;
            ull x2 = bcast2(xc);
            const ull* wr = (const ull*)&ws[(d + c) * ATTN];
#pragma unroll
            for (int a = 0; a < ATTN / 2; a++) acc[a] = ffma2u(x2, wr[a], acc[a]);
        }
    }
    if (dh == 1) {
#pragma unroll
        for (int a = 0; a < ATTN / 2; a++) {
            float2 f = unpack2(acc[a]);
            pbuf[(2 * a) * 128 + l] = f.x;
            pbuf[(2 * a + 1) * 128 + l] = f.y;
        }
    }
    __syncthreads();
    if (dh == 0) {
        float* e = (side == 0 ? g_e_rt : g_e_lt) + (size_t)(b * LL + l) * ATTN;
#pragma unroll
        for (int a = 0; a < ATTN / 2; a++) {
            float2 f = unpack2(acc[a]);
            float v0 = tanhf(f.x + pbuf[(2 * a) * 128 + l]);
            float v1 = tanhf(f.y + pbuf[(2 * a + 1) * 128 + l]);
            if (side == 0) {
                v0 *= __ldg(diag + 2 * a);
                v1 *= __ldg(diag + 2 * a + 1);
            }
            e[2 * a] = v0;
            e[2 * a + 1] = v1;
        }
    }
}

// ======================================================================
// maxpool: CTA = (b, m-group of 5). A=lt fp16, B=rt fp16 converted ONCE;
// per m only w_m -> fp16 array; w applied to B fragments via HMUL2.
// ======================================================================
#define STRD 216
#define TILE_B (LL * STRD * 2)
#define OFF_A 0
#define OFF_B (TILE_B)
#define SMEM_MP (2 * TILE_B)            // 110592
#define MGRP 5

__device__ __forceinline__ void maxpool_block(
        const float* __restrict__ lt, const float* __restrict__ rt,
        const float* __restrict__ w, float* __restrict__ out,
        int b, int mg0, char* smc, float (*red)[4], __half* w_h) {
    uint32_t sbase = smem_to_u32(smc);
    int tid = threadIdx.x, lane = tid & 31, wid = tid >> 5;

    // zero pads of both tiles
    for (int i = tid; i < 128 * 4; i += 512) {
        int r = i >> 2, c = i & 3;
        int off = (r * STRD + 200 + 2 * c) * 2;
        *(uint32_t*)(smc + OFF_A + off) = 0;
        *(uint32_t*)(smc + OFF_B + off) = 0;
    }
    // convert A = lt, B = rt once per CTA
    const float* ltb = lt + (size_t)b * LL * DD;
    const float* rtb = rt + (size_t)b * LL * DD;
    for (int i = tid; i < LL * 100; i += 512) {
        int r = i / 100, k = (i - r * 100) * 2;
        int off = (r * STRD + k) * 2;
        float2 xa = *(const float2*)(ltb + r * DD + k);
        __half2 ha = __float22half2_rn(xa);
        *(uint32_t*)(smc + OFF_A + off) = *(uint32_t*)&ha;
        float2 xb = *(const float2*)(rtb + r * DD + k);
        __half2 hb = __float22half2_rn(xb);
        *(uint32_t*)(smc + OFF_B + off) = *(uint32_t*)&hb;
    }

    int mbase = (wid >> 2) * 32, nbase = (wid & 3) * 32;
    int a_row = lane & 15;
    int a_col8 = (lane & 16) ? 8 : 0;
    int b_row = (lane & 7) + ((lane & 16) ? 8 : 0);
    int b_col8 = (lane & 8) ? 8 : 0;
    int wc = wid & 3;
    int wk = 2 * (lane & 3);

#pragma unroll 1
    for (int mg = 0; mg < MGRP; mg++) {
        int m = mg0 + mg;
        // w_m -> fp16 (208 halves incl. zero pad)
        if (tid < 104) {
            int k = tid * 2;
            __half2 hw;
            if (k < 200) {
                float2 ww = *(const float2*)(w + (size_t)m * DD + k);
                hw = __float22half2_rn(ww);
            } else {
                hw = __float2half2_rn(0.f);
            }
            *(__half2*)&w_h[k] = hw;
        }
        __syncthreads();  // covers tiles (first iter) + w_h

        float acc[2][4][4];
#pragma unroll
        for (int mt = 0; mt < 2; mt++)
#pragma unroll
            for (int nt = 0; nt < 4; nt++)
#pragma unroll
                for (int q = 0; q < 4; q++) acc[mt][nt][q] = 0.f;

#pragma unroll 1
        for (int kg = 0; kg < 13; kg++) {
            int kc = kg * 16;
            uint32_t ah[2][4];
#pragma unroll
            for (int mt = 0; mt < 2; mt++) {
                uint32_t row = mbase + 16 * mt + a_row;
                ldsm_x4(ah[mt], sbase + OFF_A + (row * STRD + kc + a_col8) * 2);
            }
            __half2 wlo = *(const __half2*)&w_h[kc + wk];
            __half2 whi = *(const __half2*)&w_h[kc + 8 + wk];
#pragma unroll
            for (int np = 0; np < 2; np++) {
                uint32_t row = nbase + np * 16 + b_row;
                uint32_t bh[4];
                ldsm_x4(bh, sbase + OFF_B + (row * STRD + kc + b_col8) * 2);
                __half2* bhh = (__half2*)bh;
                bhh[0] = __hmul2(bhh[0], wlo);
                bhh[1] = __hmul2(bhh[1], whi);
                bhh[2] = __hmul2(bhh[2], wlo);
                bhh[3] = __hmul2(bhh[3], whi);
#pragma unroll
                for (int mt = 0; mt < 2; mt++) {
                    mma16816(acc[mt][2 * np], ah[mt], bh);
                    mma16816(acc[mt][2 * np + 1], ah[mt], bh + 2);
                }
            }
        }

#pragma unroll
        for (int mt = 0; mt < 2; mt++) {
            float lo = -3.4e38f, hi = -3.4e38f;
#pragma unroll
            for (int nt = 0; nt < 4; nt++) {
                lo = fmaxf(lo, fmaxf(acc[mt][nt][0], acc[mt][nt][1]));
                hi = fmaxf(hi, fmaxf(acc[mt][nt][2], acc[mt][nt][3]));
            }
            lo = fmaxf(lo, __shfl_xor_sync(0xffffffffu, lo, 1));
            lo = fmaxf(lo, __shfl_xor_sync(0xffffffffu, lo, 2));
            hi = fmaxf(hi, __shfl_xor_sync(0xffffffffu, hi, 1));
            hi = fmaxf(hi, __shfl_xor_sync(0xffffffffu, hi, 2));
            if ((lane & 3) == 0) {
                int r = mbase + 16 * mt + (lane >> 2);
                red[r][wc] = lo;
                red[r + 8][wc] = hi;
            }
        }
        __syncthreads();
        if (tid < 128) {
            float v = fmaxf(fmaxf(red[tid][0], red[tid][1]),
                            fmaxf(red[tid][2], red[tid][3]));
            out[(size_t)(b * LL + tid) * OC + 21 + m] = tanhf(v);
        }
    }
}

// ================= branch: attnB (logits + softmax + att_lt + attentive mp) ======
__device__ __forceinline__ void attnB_block(
        const float* __restrict__ lt, const float* __restrict__ rt,
        const float* __restrict__ w_att, float* __restrict__ out,
        int b, int rh, float* sm) {
    float* Z = sm;
    float* attbuf = sm;
    float* wsT = sm + 12800;
    __half* hreg = (__half*)(sm + 16800);
    __half* ers_h = hreg;
    __half* elts_h = hreg + 4608;
    __half* Zh = hreg;
    __half* ltsT = hreg + 8704;
    int tid = threadIdx.x, lane = tid & 31, wid = tid >> 5;

    for (int i = tid; i < DD * MPP; i += 512) {
        int d = i / MPP, m = i - d * MPP;
        wsT[d * MPP + m] = w_att[m * DD + d];
    }
    const float* ersrc = g_e_rt + ((size_t)b * LL + rh * 64) * ATTN;
    for (int i = tid; i < 64 * 36; i += 512) {
        int r = i / 36, kk = (i - r * 36) * 2;
        float v0 = (kk < 50) ? ersrc[r * 50 + kk] : 0.f;
        float v1 = (kk + 1 < 50) ? ersrc[r * 50 + kk + 1] : 0.f;
        *(__half2*)&ers_h[r * 72 + kk] = __float22half2_rn(make_float2(v0, v1));
    }
    const float* elsrc = g_e_lt + (size_t)b * LL * ATTN;
    for (int i = tid; i < 128 * 36; i += 512) {
        int r = i / 36, kk = (i - r * 36) * 2;
        float v0 = (kk < 50) ? elsrc[r * 50 + kk] : 0.f;
        float v1 = (kk + 1 < 50) ? elsrc[r * 50 + kk + 1] : 0.f;
        *(__half2*)&elts_h[r * 72 + kk] = __float22half2_rn(make_float2(v0, v1));
    }
    __syncthreads();

    uint32_t ers_b = smem_to_u32(ers_h);
    uint32_t elts_b = smem_to_u32(elts_h);
    uint32_t zh_b = smem_to_u32(Zh);
    uint32_t ltsT_b = smem_to_u32(ltsT);

    int wm = wid >> 2, wn = wid & 3;
    int mbase = wm * 16;
    int a_row = lane & 15;
    int a_col8 = (lane & 16) ? 8 : 0;
    int b_row = (lane & 7) + ((lane & 16) ? 8 : 0);
    int b_col8 = (lane & 8) ? 8 : 0;

    // phase 1: Z[64x128] = ers @ elts^T (K=64)
    {
        int nbase = wn * 32;
        float acc[4][4];
#pragma unroll
        for (int t = 0; t < 4; t++)
#pragma unroll
            for (int q = 0; q < 4; q++) acc[t][q] = 0.f;
#pragma unroll
        for (int kt = 0; kt < 4; kt++) {
            uint32_t a[4];
            ldsm_x4(a, ers_b + ((mbase + a_row) * 72 + kt * 16 + a_col8) * 2);
#pragma unroll
            for (int np = 0; np < 2; np++) {
                uint32_t bh[4];
                ldsm_x4(bh, elts_b + ((nbase + np * 16 + b_row) * 72 + kt * 16 + b_col8) * 2);
                mma16816(acc[2 * np], a, bh);
                mma16816(acc[2 * np + 1], a, bh + 2);
            }
        }
        int rr = mbase + (lane >> 2);
#pragma unroll
        for (int t = 0; t < 4; t++) {
            int c = nbase + t * 8 + 2 * (lane & 3);
            Z[rr * 129 + c] = acc[t][0];
            Z[rr * 129 + c + 1] = acc[t][1];
            Z[(rr + 8) * 129 + c] = acc[t][2];
            Z[(rr + 8) * 129 + c + 1] = acc[t][3];
        }
    }
    __syncthreads();

    if (tid < 256) {
        int r = tid >> 2, h = tid & 3;
        float* zr = Z + r * 129 + h * 32;
        float mx = zr[0];
#pragma unroll 4
        for (int k = 1; k < 32; k++) mx = fmaxf(mx, zr[k]);
        mx = fmaxf(mx, __shfl_xor_sync(0xffffffffu, mx, 1));
        mx = fmaxf(mx, __shfl_xor_sync(0xffffffffu, mx, 2));
        float s = 0.f;
#pragma unroll 4
        for (int k = 0; k < 32; k++) {
            float e = expf(zr[k] - mx);
            zr[k] = e;
            s += e;
        }
        s += __shfl_xor_sync(0xffffffffu, s, 1);
        s += __shfl_xor_sync(0xffffffffu, s, 2);
        float inv = 1.f / s;
#pragma unroll 4
        for (int k = 0; k < 32; k++) zr[k] *= inv;
    }
    __syncthreads();

    {
        float zreg[8];
        int r = tid >> 3, kp = (tid & 7) * 16;
#pragma unroll
        for (int t = 0; t < 8; t++) zreg[t] = Z[r * 129 + kp + 2 * t];
        float zreg2[8];
#pragma unroll
        for (int t = 0; t < 8; t++) zreg2[t] = Z[r * 129 + kp + 2 * t + 1];
        __syncthreads();
#pragma unroll
        for (int t = 0; t < 8; t++)
            *(__half2*)&Zh[r * 136 + kp + 2 * t] =
                __float22half2_rn(make_float2(zreg[t], zreg2[t]));
    }
    __syncthreads();

    const float* ltb = lt + (size_t)b * LL * DD;
    for (int s = 0; s < 4; s++) {
        for (int i = tid; i < 64 * 64; i += 512) {
            int dl = i & 63, lp = (i >> 6) * 2;
            int d = s * 64 + dl;
            float v0 = 0.f, v1 = 0.f;
            if (d < 200) {
                v0 = __ldg(ltb + lp * DD + d);
                v1 = __ldg(ltb + (lp + 1) * DD + d);
            }
            *(__half2*)&ltsT[dl * 136 + lp] = __float22half2_rn(make_float2(v0, v1));
        }
        __syncthreads();

        int nbase = wn * 16;
        float acc[2][4];
#pragma unroll
        for (int t = 0; t < 2; t++)
#pragma unroll
            for (int q = 0; q < 4; q++) acc[t][q] = 0.f;
#pragma unroll
        for (int kt = 0; kt < 8; kt++) {
            uint32_t a[4];
            ldsm_x4(a, zh_b + ((mbase + a_row) * 136 + kt * 16 + a_col8) * 2);
            uint32_t bh[4];
            ldsm_x4(bh, ltsT_b + ((nbase + b_row) * 136 + kt * 16 + b_col8) * 2);
            mma16816(acc[0], a, bh);
            mma16816(acc[1], a, bh + 2);
        }
        int rr = mbase + (lane >> 2);
#pragma unroll
        for (int t = 0; t < 2; t++) {
            int d = s * 64 + nbase + t * 8 + 2 * (lane & 3);
            if (d < 200) {
                attbuf[rr * DD + d] = acc[t][0];
                attbuf[rr * DD + d + 1] = acc[t][1];
                attbuf[(rr + 8) * DD + d] = acc[t][2];
                attbuf[(rr + 8) * DD + d + 1] = acc[t][3];
            }
        }
        __syncthreads();
    }

    {
        int l = tid >> 3, q = tid & 7;
        int row = rh * 64 + l;
        const float* xp = attbuf + l * DD + q * 25;
        const float* yp = rt + (size_t)(b * LL + row) * DD + q * 25;
        float cos_acc = 0.f;
        ull macc[MPP / 2];
#pragma unroll
        for (int mm = 0; mm < MPP / 2; mm++) macc[mm] = 0ULL;
#pragma unroll
        for (int i = 0; i < 25; i++) {
            float p = xp[i] * __ldg(yp + i);
            cos_acc += p;
            ull pb = bcast2(p);
            const ull* wr = (const ull*)&wsT[(q * 25 + i) * MPP];
#pragma unroll
            for (int mm = 0; mm < MPP / 2; mm++) macc[mm] = ffma2u(pb, wr[mm], macc[mm]);
        }
        cos_acc += __shfl_xor_sync(0xffffffffu, cos_acc, 1);
        cos_acc += __shfl_xor_sync(0xffffffffu, cos_acc, 2);
        cos_acc += __shfl_xor_sync(0xffffffffu, cos_acc, 4);
#pragma unroll
        for (int mm = 0; mm < MPP / 2; mm++) {
            macc[mm] = addp2(macc[mm], __shfl_xor_sync(0xffffffffu, macc[mm], 1));
            macc[mm] = addp2(macc[mm], __shfl_xor_sync(0xffffffffu, macc[mm], 2));
            macc[mm] = addp2(macc[mm], __shfl_xor_sync(0xffffffffu, macc[mm], 4));
        }
        if (q == 0) {
            float* o = out + (size_t)(b * LL + row) * OC + 41;
            o[0] = tanhf(cos_acc);
#pragma unroll
            for (int mm = 0; mm < MPP / 2; mm++) {
                float2 f = unpack2(macc[mm]);
                o[1 + 2 * mm] = tanhf(f.x);
                o[2 + 2 * mm] = tanhf(f.y);
            }
        }
    }
}

// ================= branch: full match (cols [0,21)) =================
__device__ __forceinline__ void full_block(
        const float* __restrict__ lt, const float* __restrict__ fw,
        const float* __restrict__ bw, const float* __restrict__ wf,
        float* __restrict__ out, int b, float* sm) {
    float* hw = sm;
    int tid = threadIdx.x;
    for (int idx = tid; idx < (MPP + 1) * DD; idx += 512) {
        int mm = idx / DD, d = idx - mm * DD;
        float hv = (d < DD / 2) ? fw[b * (DD / 2) + d] : bw[b * (DD / 2) + d - DD / 2];
        hw[idx] = (mm == 0) ? hv : wf[(mm - 1) * DD + d] * hv;
    }
    __syncthreads();
    if (tid < 128) {
        const ull* row = (const ull*)(lt + (size_t)(b * LL + tid) * DD);
        ull acc[MPP + 1];
#pragma unroll
        for (int mm = 0; mm <= MPP; mm++) acc[mm] = 0ULL;
        for (int d2 = 0; d2 < DD / 2; d2++) {
            ull x = __ldg(row + d2);
#pragma unroll
            for (int mm = 0; mm <= MPP; mm++)
                acc[mm] = ffma2u(x, *(const ull*)&hw[mm * DD + 2 * d2], acc[mm]);
        }
        float* o = out + (size_t)(b * LL + tid) * OC;
#pragma unroll
        for (int mm = 0; mm <= MPP; mm++) {
            float2 f = unpack2(acc[mm]);
            o[mm] = tanhf(f.x + f.y);
        }
    }
}

// ======= branch: max-attentive via fp16 mma + exact top-candidate rescore =======
#define MA_MARGIN 0.02f
__device__ __forceinline__ void maxatt_block(
        const float* __restrict__ lt, const float* __restrict__ rt,
        const float* __restrict__ w_maxatt, float* __restrict__ out,
        int b, int rh, char* smc) {
    uint32_t sbase = smem_to_u32(smc);
    float* nlt = (float*)(smc + 82944);
    float* wmax = (float*)(smc + 83456);
    float* rowmax = (float*)(smc + 84480);
    int* cnt = (int*)(smc + 84736);
    int* cand = (int*)(smc + 84992);
    int* pos = (int*)(smc + 87040);
    float* wsT = (float*)(smc + 87296);
    int tid = threadIdx.x, lane = tid & 31, wid = tid >> 5;

    if (tid < 128) {
        const float4* p = (const float4*)(lt + (size_t)(b * LL + tid) * DD);
        float s = 0.f;
        for (int i = 0; i < DD / 4; i++) {
            float4 v = __ldg(p + i);
            s += v.x * v.x + v.y * v.y + v.z * v.z + v.w * v.w;
        }
        nlt[tid] = rsqrtf(fmaxf(s, 1e-6f));
    }
    if (tid < 64) cnt[tid] = 0;
    for (int i = tid; i < DD * MPP; i += 512) {
        int d = i / MPP, m = i - d * MPP;
        wsT[d * MPP + m] = w_maxatt[m * DD + d];
    }
    for (int i = tid; i < (64 + 128) * 4; i += 512) {
        int rr = i >> 2, c = i & 3;
        if (rr < 64)
            *(uint32_t*)(smc + (rr * STRD + 200 + 2 * c) * 2) = 0;
        else
            *(uint32_t*)(smc + 27648 + ((rr - 64) * STRD + 200 + 2 * c) * 2) = 0;
    }
    const float* rtb = rt + ((size_t)b * LL + rh * 64) * DD;
    for (int i = tid; i < 64 * 100; i += 512) {
        int r = i / 100, k = (i - r * 100) * 2;
        float2 x = *(const float2*)(rtb + r * DD + k);
        __half2 h2 = __float22half2_rn(x);
        *(uint32_t*)(smc + (r * STRD + k) * 2) = *(uint32_t*)&h2;
    }
    const float* ltb = lt + (size_t)b * LL * DD;
    for (int i = tid; i < 128 * 100; i += 512) {
        int r = i / 100, k = (i - r * 100) * 2;
        float2 x = *(const float2*)(ltb + r * DD + k);
        __half2 h2 = __float22half2_rn(x);
        *(uint32_t*)(smc + 27648 + (r * STRD + k) * 2) = *(uint32_t*)&h2;
    }
    __syncthreads();

    int wm = wid >> 2, wn = wid & 3;
    int mbase = wm * 16, nbase = wn * 32;
    int a_row = lane & 15;
    int a_col8 = (lane & 16) ? 8 : 0;
    int b_row = (lane & 7) + ((lane & 16) ? 8 : 0);
    int b_col8 = (lane & 8) ? 8 : 0;
    float acc[4][4];
#pragma unroll
    for (int t = 0; t < 4; t++)
#pragma unroll
        for (int q = 0; q < 4; q++) acc[t][q] = 0.f;
#pragma unroll 1
    for (int kg = 0; kg < 13; kg++) {
        int kc = kg * 16;
        uint32_t a[4];
        ldsm_x4(a, sbase + ((mbase + a_row) * STRD + kc + a_col8) * 2);
#pragma unroll
        for (int np = 0; np < 2; np++) {
            uint32_t bh[4];
            ldsm_x4(bh, sbase + 27648 + ((nbase + np * 16 + b_row) * STRD + kc + b_col8) * 2);
            mma16816(acc[2 * np], a, bh);
            mma16816(acc[2 * np + 1], a, bh + 2);
        }
    }
    int rr = mbase + (lane >> 2);
    float vlo = -3.4e38f, vhi = -3.4e38f;
#pragma unroll
    for (int t = 0; t < 4; t++) {
        int c = nbase + t * 8 + 2 * (lane & 3);
        acc[t][0] *= nlt[c];
        acc[t][1] *= nlt[c + 1];
        acc[t][2] *= nlt[c];
        acc[t][3] *= nlt[c + 1];
        vlo = fmaxf(vlo, fmaxf(acc[t][0], acc[t][1]));
        vhi = fmaxf(vhi, fmaxf(acc[t][2], acc[t][3]));
    }
    vlo = fmaxf(vlo, __shfl_xor_sync(0xffffffffu, vlo, 1));
    vlo = fmaxf(vlo, __shfl_xor_sync(0xffffffffu, vlo, 2));
    vhi = fmaxf(vhi, __shfl_xor_sync(0xffffffffu, vhi, 1));
    vhi = fmaxf(vhi, __shfl_xor_sync(0xffffffffu, vhi, 2));
    if ((lane & 3) == 0) {
        wmax[rr * 4 + wn] = vlo;
        wmax[(rr + 8) * 4 + wn] = vhi;
    }
    __syncthreads();
    if (tid < 64)
        rowmax[tid] = fmaxf(fmaxf(wmax[tid * 4], wmax[tid * 4 + 1]),
                            fmaxf(wmax[tid * 4 + 2], wmax[tid * 4 + 3]));
    __syncthreads();
    {
        float thr_lo = rowmax[rr] - MA_MARGIN;
        float thr_hi = rowmax[rr + 8] - MA_MARGIN;
#pragma unroll
        for (int t = 0; t < 4; t++) {
            int c = nbase + t * 8 + 2 * (lane & 3);
            if (acc[t][0] >= thr_lo) {
                int s = atomicAdd(&cnt[rr], 1);
                if (s < 8) cand[rr * 8 + s] = c;
            }
            if (acc[t][1] >= thr_lo) {
                int s = atomicAdd(&cnt[rr], 1);
                if (s < 8) cand[rr * 8 + s] = c + 1;
            }
            if (acc[t][2] >= thr_hi) {
                int s = atomicAdd(&cnt[rr + 8], 1);
                if (s < 8) cand[(rr + 8) * 8 + s] = c;
            }
            if (acc[t][3] >= thr_hi) {
                int s = atomicAdd(&cnt[rr + 8], 1);
                if (s < 8) cand[(rr + 8) * 8 + s] = c + 1;
            }
        }
    }
    __syncthreads();
    for (int rq = 0; rq < 4; rq++) {
        int r = wid * 4 + rq;
        int n = min(cnt[r], 8);
        const float* rtrow = rt + ((size_t)b * LL + rh * 64 + r) * DD;
        float best = -3.4e38f;
        int bi = 1 << 30;
        for (int j = 0; j < n; j++) {
            int c = cand[r * 8 + j];
            const float* ltrow = lt + ((size_t)b * LL + c) * DD;
            float s = 0.f;
            for (int k = lane; k < DD; k += 32) s += rtrow[k] * ltrow[k];
            s += __shfl_xor_sync(0xffffffffu, s, 16);
            s += __shfl_xor_sync(0xffffffffu, s, 8);
            s += __shfl_xor_sync(0xffffffffu, s, 4);
            s += __shfl_xor_sync(0xffffffffu, s, 2);
            s += __shfl_xor_sync(0xffffffffu, s, 1);
            float rel = s * nlt[c];
            if (rel > best || (rel == best && c < bi)) {
                best = rel;
                bi = c;
            }
        }
        if (lane == 0) pos[r] = bi;
    }
    __syncthreads();
    if (tid < 256) {
        int l = tid >> 2, q = tid & 3;
        int row = rh * 64 + l;
        const float2* xp = (const float2*)(rt + (size_t)(b * LL + row) * DD + q * 50);
        const float2* yp = (const float2*)(lt + (size_t)(b * LL + pos[l]) * DD + q * 50);
        float cos_acc = 0.f;
        ull macc[MPP / 2];
#pragma unroll
        for (int mm = 0; mm < MPP / 2; mm++) macc[mm] = 0ULL;
#pragma unroll
        for (int i = 0; i < 25; i++) {
            float2 x = __ldg(xp + i);
            float2 y = __ldg(yp + i);
            float p0 = x.x * y.x, p1 = x.y * y.y;
            cos_acc += p0 + p1;
            int d = q * 50 + 2 * i;
            ull pb0 = bcast2(p0), pb1 = bcast2(p1);
            const ull* w0 = (const ull*)&wsT[d * MPP];
            const ull* w1 = (const ull*)&wsT[(d + 1) * MPP];
#pragma unroll
            for (int mm = 0; mm < MPP / 2; mm++) {
                macc[mm] = ffma2u(pb0, w0[mm], macc[mm]);
                macc[mm] = ffma2u(pb1, w1[mm], macc[mm]);
            }
        }
        cos_acc += __shfl_xor_sync(0xffffffffu, cos_acc, 1);
        cos_acc += __shfl_xor_sync(0xffffffffu, cos_acc, 2);
#pragma unroll
        for (int mm = 0; mm < MPP / 2; mm++) {
            macc[mm] = addp2(macc[mm], __shfl_xor_sync(0xffffffffu, macc[mm], 1));
            macc[mm] = addp2(macc[mm], __shfl_xor_sync(0xffffffffu, macc[mm], 2));
        }
        if (q == 0) {
            float* o = out + (size_t)(b * LL + row) * OC + 62;
            o[0] = tanhf(cos_acc);
#pragma unroll
            for (int mm = 0; mm < MPP / 2; mm++) {
                float2 f = unpack2(macc[mm]);
                o[1 + 2 * mm] = tanhf(f.x);
                o[2 + 2 * mm] = tanhf(f.y);
            }
        }
    }
}

// ================= mega: everything except proj =================
#define GRID_MP (BB * (MPP / MGRP))     // 256
#define GRID_MEGA (GRID_MP + 2 * BB + 2 * BB + BB)   // 576

__global__ __launch_bounds__(512, 2) void mega(
        const float* __restrict__ lt, const float* __restrict__ rt,
        const float* __restrict__ fw, const float* __restrict__ bw,
        const float* __restrict__ w_full, const float* __restrict__ w_maxpool,
        const float* __restrict__ w_att, const float* __restrict__ w_maxatt,
        float* __restrict__ out) {
    extern __shared__ char smc[];
    __shared__ float red[128][4];
    __shared__ __half w_h[224];
    int bx = blockIdx.x;
    if (bx < GRID_MP) {
        maxpool_block(lt, rt, w_maxpool, out, bx >> 2, (bx & 3) * MGRP, smc, red, w_h);
    } else if (bx < GRID_MP + 2 * BB) {
        int i = bx - GRID_MP;
        maxatt_block(lt, rt, w_maxatt, out, i >> 1, i & 1, smc);
    } else if (bx < GRID_MP + 4 * BB) {
        int i = bx - GRID_MP - 2 * BB;
        attnB_block(lt, rt, w_att, out, i >> 1, i & 1, (float*)smc);
    } else {
        full_block(lt, fw, bw, w_full, out, bx - GRID_MP - 4 * BB, (float*)smc);
    }
}

// ================= launch =================
extern "C" void kernel_launch(void* const* d_in, const int* in_sizes, int n_in,
                              void* d_out, int out_size) {
    const float* reps_lt = (const float*)d_in[0];
    const float* reps_rt = (const float*)d_in[1];
    const float* fw_h = (const float*)d_in[2];
    const float* bw_h = (const float*)d_in[3];
    const float* w_full = (const float*)d_in[4];
    const float* w_maxpool = (const float*)d_in[5];
    const float* w_att = (const float*)d_in[6];
    const float* w_maxatt = (const float*)d_in[7];
    const float* attn_w1 = (const float*)d_in[8];
    const float* attn_w2 = (const float*)d_in[9];
    const float* diag_w = (const float*)d_in[10];
    float* out = (float*)d_out;

    cudaFuncSetAttribute(projK, cudaFuncAttributeMaxDynamicSharedMemorySize, SMEM_PROJ);
    cudaFuncSetAttribute(mega, cudaFuncAttributeMaxDynamicSharedMemorySize, SMEM_MP);

    projK<<<dim3(BB, 2), 256, SMEM_PROJ>>>(reps_lt, reps_rt, attn_w1, attn_w2, diag_w);
    mega<<<GRID_MEGA, 512, SMEM_MP>>>(reps_lt, reps_rt, fw_h, bw_h, w_full,
                                      w_maxpool, w_att, w_maxatt, out);
}